// round 1
// baseline (speedup 1.0000x reference)
#include <cuda_runtime.h>

#define NN 50000
#define EE 800000
#define TOT (EE + NN)
#define HC 128
#define HH 4
#define CC 32
#define NEG_SLOPE 0.2f

// ---------------- scratch (device globals; no allocs allowed) ----------------
__device__ float g_xp[(size_t)NN * HC];   // projected features (per layer)
__device__ float g_h[(size_t)NN * HC];    // layer-1 output (post relu)
__device__ float g_as[NN * HH];           // alpha_src per node/head
__device__ float g_ad[NN * HH];           // alpha_dst per node/head
__device__ int   g_deg[NN];
__device__ int   g_off[NN + 1];
__device__ int   g_pos[NN];
__device__ int   g_csr[TOT];              // src ids grouped by dst

__device__ __forceinline__ float leaky(float x) { return x > 0.f ? x : NEG_SLOPE * x; }

// ---------------- CSR build ----------------
__global__ void zero_deg_kernel() {
    int i = blockIdx.x * blockDim.x + threadIdx.x;
    if (i < NN) g_deg[i] = 0;
}

__global__ void count_kernel(const int* __restrict__ ei) {
    int t = blockIdx.x * blockDim.x + threadIdx.x;
    if (t >= TOT) return;
    int d = (t < EE) ? ei[EE + t] : (t - EE);
    atomicAdd(&g_deg[d], 1);
}

__global__ void scan_kernel() {
    __shared__ int wsum[32];
    __shared__ int carry;
    int tid = threadIdx.x, lane = tid & 31, wid = tid >> 5;
    if (tid == 0) carry = 0;
    __syncthreads();
    for (int base = 0; base < NN; base += 1024) {
        int idx = base + tid;
        int v = (idx < NN) ? g_deg[idx] : 0;
        int x = v;
#pragma unroll
        for (int o = 1; o < 32; o <<= 1) {
            int y = __shfl_up_sync(0xffffffffu, x, o);
            if (lane >= o) x += y;
        }
        if (lane == 31) wsum[wid] = x;
        __syncthreads();
        if (wid == 0) {
            int t2 = wsum[lane];
#pragma unroll
            for (int o = 1; o < 32; o <<= 1) {
                int y = __shfl_up_sync(0xffffffffu, t2, o);
                if (lane >= o) t2 += y;
            }
            wsum[lane] = t2;
        }
        __syncthreads();
        int blockIncl = x + (wid > 0 ? wsum[wid - 1] : 0);
        int excl = carry + blockIncl - v;
        if (idx < NN) { g_off[idx] = excl; g_pos[idx] = excl; }
        __syncthreads();
        if (tid == 1023) carry += wsum[31];
    }
    __syncthreads();
    if (tid == 0) g_off[NN] = carry;
}

__global__ void fill_kernel(const int* __restrict__ ei) {
    int t = blockIdx.x * blockDim.x + threadIdx.x;
    if (t >= TOT) return;
    int s, d;
    if (t < EE) { s = ei[t]; d = ei[EE + t]; }
    else { s = d = t - EE; }
    int p = atomicAdd(&g_pos[d], 1);
    g_csr[p] = s;
}

// ---------------- GEMM: C[M,128] = A[M,K] @ B[K,128] ----------------
template <int K>
__global__ void __launch_bounds__(256) gemm_kernel(const float* __restrict__ A,
                                                   const float* __restrict__ B,
                                                   float* __restrict__ Cmat, int M) {
    const int BM = 64, BN = 128, BK = 32;
    __shared__ float As[BK][BM + 1];
    __shared__ float Bs[BK][BN];
    int tid = threadIdx.x;
    int tx = tid & 15, ty = tid >> 4;
    int rowBase = blockIdx.x * BM;
    float acc[4][8];
#pragma unroll
    for (int i = 0; i < 4; i++)
#pragma unroll
        for (int j = 0; j < 8; j++) acc[i][j] = 0.f;

    for (int k0 = 0; k0 < K; k0 += BK) {
#pragma unroll
        for (int i = 0; i < 8; i++) {
            int idx = tid + i * 256;
            int r = idx >> 5, kk = idx & 31;
            int gr = rowBase + r;
            As[kk][r] = (gr < M) ? A[(size_t)gr * K + k0 + kk] : 0.f;
        }
#pragma unroll
        for (int i = 0; i < 16; i++) {
            int idx = tid + i * 256;
            int r = idx >> 7, c = idx & 127;
            Bs[r][c] = B[(size_t)(k0 + r) * BN + c];
        }
        __syncthreads();
#pragma unroll
        for (int kk = 0; kk < BK; kk++) {
            float a[4], b[8];
#pragma unroll
            for (int ii = 0; ii < 4; ii++) a[ii] = As[kk][ty + 16 * ii];
#pragma unroll
            for (int j = 0; j < 8; j++) b[j] = Bs[kk][tx + 16 * j];
#pragma unroll
            for (int ii = 0; ii < 4; ii++)
#pragma unroll
                for (int j = 0; j < 8; j++) acc[ii][j] = fmaf(a[ii], b[j], acc[ii][j]);
        }
        __syncthreads();
    }
#pragma unroll
    for (int ii = 0; ii < 4; ii++) {
        int r = rowBase + ty + 16 * ii;
        if (r < M) {
#pragma unroll
            for (int j = 0; j < 8; j++) Cmat[(size_t)r * BN + tx + 16 * j] = acc[ii][j];
        }
    }
}

// ---------------- per-node attention coefficients ----------------
__global__ void alpha_kernel(const float* __restrict__ xp,
                             const float* __restrict__ a_src,
                             const float* __restrict__ a_dst) {
    int warp = (blockIdx.x * blockDim.x + threadIdx.x) >> 5;
    int lane = threadIdx.x & 31;
    if (warp >= NN) return;
    float s[4], d[4];
#pragma unroll
    for (int j = 0; j < 4; j++) {
        float v = xp[(size_t)warp * HC + j * 32 + lane];
        s[j] = v * a_src[j * 32 + lane];
        d[j] = v * a_dst[j * 32 + lane];
    }
#pragma unroll
    for (int o = 16; o; o >>= 1) {
#pragma unroll
        for (int j = 0; j < 4; j++) {
            s[j] += __shfl_xor_sync(0xffffffffu, s[j], o);
            d[j] += __shfl_xor_sync(0xffffffffu, d[j], o);
        }
    }
    if (lane == 0) {
#pragma unroll
        for (int j = 0; j < 4; j++) {
            g_as[warp * HH + j] = s[j];
            g_ad[warp * HH + j] = d[j];
        }
    }
}

// ---------------- softmax + aggregate (one warp per dst node) ----------------
template <bool ROOTS, bool RELU>
__global__ void agg_kernel(const float* __restrict__ xp,
                           const float* __restrict__ bias,
                           const int* __restrict__ roots,
                           float* __restrict__ out, int n_items) {
    int warp = (blockIdx.x * blockDim.x + threadIdx.x) >> 5;
    int lane = threadIdx.x & 31;
    if (warp >= n_items) return;
    int node = ROOTS ? roots[warp] : warp;
    int beg = g_off[node], end = g_off[node + 1];

    float4 adv = ((const float4*)g_ad)[node];

    // pass 1: per-head max logit
    float m0 = -1e30f, m1 = -1e30f, m2 = -1e30f, m3 = -1e30f;
    for (int e = beg + lane; e < end; e += 32) {
        int s = g_csr[e];
        float4 av = ((const float4*)g_as)[s];
        m0 = fmaxf(m0, leaky(av.x + adv.x));
        m1 = fmaxf(m1, leaky(av.y + adv.y));
        m2 = fmaxf(m2, leaky(av.z + adv.z));
        m3 = fmaxf(m3, leaky(av.w + adv.w));
    }
#pragma unroll
    for (int o = 16; o; o >>= 1) {
        m0 = fmaxf(m0, __shfl_xor_sync(0xffffffffu, m0, o));
        m1 = fmaxf(m1, __shfl_xor_sync(0xffffffffu, m1, o));
        m2 = fmaxf(m2, __shfl_xor_sync(0xffffffffu, m2, o));
        m3 = fmaxf(m3, __shfl_xor_sync(0xffffffffu, m3, o));
    }
    int h = lane >> 3;  // 8 lanes per head, 4 floats per lane
    float myad  = (h == 0) ? adv.x : (h == 1) ? adv.y : (h == 2) ? adv.z : adv.w;
    float mymax = (h == 0) ? m0 : (h == 1) ? m1 : (h == 2) ? m2 : m3;

    // pass 2: weighted accumulate + denominator
    float4 acc = make_float4(0.f, 0.f, 0.f, 0.f);
    float denom = 0.f;
    for (int e = beg; e < end; ++e) {
        int s = g_csr[e];
        float als = g_as[s * HH + h];
        float w = __expf(leaky(als + myad) - mymax);
        float4 v = ((const float4*)xp)[(size_t)s * 32 + lane];
        acc.x = fmaf(w, v.x, acc.x);
        acc.y = fmaf(w, v.y, acc.y);
        acc.z = fmaf(w, v.z, acc.z);
        acc.w = fmaf(w, v.w, acc.w);
        denom += w;
    }
    float inv = 1.f / (denom + 1e-16f);
    float4 bv = ((const float4*)bias)[lane];
    float4 r;
    r.x = acc.x * inv + bv.x;
    r.y = acc.y * inv + bv.y;
    r.z = acc.z * inv + bv.z;
    r.w = acc.w * inv + bv.w;
    if (RELU) {
        r.x = fmaxf(r.x, 0.f); r.y = fmaxf(r.y, 0.f);
        r.z = fmaxf(r.z, 0.f); r.w = fmaxf(r.w, 0.f);
    }
    int orow = ROOTS ? warp : node;
    ((float4*)out)[(size_t)orow * 32 + lane] = r;
}

// ---------------- launch ----------------
extern "C" void kernel_launch(void* const* d_in, const int* in_sizes, int n_in,
                              void* d_out, int out_size) {
    const float* x     = (const float*)d_in[0];
    const int*   ei    = (const int*)d_in[1];
    const int*   roots = (const int*)d_in[2];
    const float* W1    = (const float*)d_in[3];
    const float* as1   = (const float*)d_in[4];
    const float* ad1   = (const float*)d_in[5];
    const float* b1    = (const float*)d_in[6];
    const float* W2    = (const float*)d_in[7];
    const float* as2   = (const float*)d_in[8];
    const float* ad2   = (const float*)d_in[9];
    const float* b2    = (const float*)d_in[10];
    float* out = (float*)d_out;

    float *p_xp, *p_h;
    cudaGetSymbolAddress((void**)&p_xp, g_xp);
    cudaGetSymbolAddress((void**)&p_h, g_h);

    // CSR over dst (shared by both layers)
    zero_deg_kernel<<<(NN + 255) / 256, 256>>>();
    count_kernel<<<(TOT + 255) / 256, 256>>>(ei);
    scan_kernel<<<1, 1024>>>();
    fill_kernel<<<(TOT + 255) / 256, 256>>>(ei);

    // layer 1
    gemm_kernel<256><<<(NN + 63) / 64, 256>>>(x, W1, p_xp, NN);
    alpha_kernel<<<(NN + 7) / 8, 256>>>(p_xp, as1, ad1);
    agg_kernel<false, true><<<(NN + 7) / 8, 256>>>(p_xp, b1, nullptr, p_h, NN);

    // layer 2 (aggregation only needed at the 1024 root nodes)
    gemm_kernel<128><<<(NN + 63) / 64, 256>>>(p_h, W2, p_xp, NN);
    alpha_kernel<<<(NN + 7) / 8, 256>>>(p_xp, as2, ad2);
    agg_kernel<true, false><<<(1024 + 7) / 8, 256>>>(p_xp, b2, roots, out, 1024);
}

// round 5
// speedup vs baseline: 1.0121x; 1.0121x over previous
#include <cuda_runtime.h>

#define NN 50000
#define EE 800000
#define TOT (EE + NN)
#define HC 128
#define HH 4
#define NEG_SLOPE 0.2f

// ---------------- scratch (device globals; no allocs allowed) ----------------
__device__ float g_xp[(size_t)NN * HC];   // projected features (per layer)
__device__ float g_h[(size_t)NN * HC];    // layer-1 output (post relu)
__device__ float g_as[NN * HH];           // alpha_src per node/head
__device__ float g_ad[NN * HH];           // alpha_dst per node/head
__device__ int   g_deg[NN];
__device__ int   g_off[NN + 1];
__device__ int   g_pos[NN];
__device__ int   g_csr[TOT];              // src ids grouped by dst (restricted)
__device__ unsigned char g_flagR[NN];     // is root
__device__ unsigned char g_flagL[NN];     // in L1set (roots + sources of roots)
__device__ int   g_list[NN];              // compacted L1set
__device__ int   g_cnt;

__device__ __forceinline__ float leaky(float x) { return x > 0.f ? x : NEG_SLOPE * x; }

// ---------------- frontier marking ----------------
__global__ void init_kernel() {
    int i = blockIdx.x * blockDim.x + threadIdx.x;
    if (i < NN) { g_flagR[i] = 0; g_flagL[i] = 0; g_deg[i] = 0; }
    if (i == 0) g_cnt = 0;
}

__global__ void mark_roots_kernel(const int* __restrict__ roots) {
    int i = blockIdx.x * blockDim.x + threadIdx.x;
    if (i < 1024) { int r = roots[i]; g_flagR[r] = 1; g_flagL[r] = 1; }
}

__global__ void mark_src_kernel(const int* __restrict__ ei) {
    int e = blockIdx.x * blockDim.x + threadIdx.x;
    if (e >= EE) return;
    int d = ei[EE + e];
    if (g_flagR[d]) g_flagL[ei[e]] = 1;
}

__global__ void compact_kernel() {
    int i = blockIdx.x * blockDim.x + threadIdx.x;
    if (i < NN && g_flagL[i]) {
        int p = atomicAdd(&g_cnt, 1);
        g_list[p] = i;
    }
}

// ---------------- CSR build (restricted to dst in L1set) ----------------
__global__ void count_kernel(const int* __restrict__ ei) {
    int t = blockIdx.x * blockDim.x + threadIdx.x;
    if (t >= TOT) return;
    int d = (t < EE) ? ei[EE + t] : (t - EE);
    if (g_flagL[d]) atomicAdd(&g_deg[d], 1);
}

__global__ void scan_kernel() {
    const int CH = 49;  // 1024 * 49 >= NN
    int tid = threadIdx.x, lane = tid & 31, wid = tid >> 5;
    int base = tid * CH;
    int sum = 0;
    for (int i = 0; i < CH; i++) {
        int idx = base + i;
        if (idx < NN) sum += g_deg[idx];
    }
    int x = sum;
#pragma unroll
    for (int o = 1; o < 32; o <<= 1) {
        int y = __shfl_up_sync(0xffffffffu, x, o);
        if (lane >= o) x += y;
    }
    __shared__ int ws[32];
    if (lane == 31) ws[wid] = x;
    __syncthreads();
    if (wid == 0) {
        int t2 = ws[lane];
#pragma unroll
        for (int o = 1; o < 32; o <<= 1) {
            int y = __shfl_up_sync(0xffffffffu, t2, o);
            if (lane >= o) t2 += y;
        }
        ws[lane] = t2;
    }
    __syncthreads();
    int excl = x - sum + (wid ? ws[wid - 1] : 0);
    int run = excl;
    for (int i = 0; i < CH; i++) {
        int idx = base + i;
        if (idx < NN) {
            int d = g_deg[idx];
            g_off[idx] = run;
            g_pos[idx] = run;
            run += d;
        }
    }
    if (tid == 1023) g_off[NN] = run;
}

__global__ void fill_kernel(const int* __restrict__ ei) {
    int t = blockIdx.x * blockDim.x + threadIdx.x;
    if (t >= TOT) return;
    int s, d;
    if (t < EE) { s = ei[t]; d = ei[EE + t]; }
    else { s = d = t - EE; }
    if (!g_flagL[d]) return;
    int p = atomicAdd(&g_pos[d], 1);
    g_csr[p] = s;
}

// ---------------- GEMM: C[M,128] = A[M,K] @ B[K,128], optional row gather/scatter ----
template <int K, bool GATHER>
__global__ void __launch_bounds__(256, 2)
gemm_kernel(const float* __restrict__ A, const float* __restrict__ B,
            float* __restrict__ Cmat, int M) {
    __shared__ float As[2][8][128];
    __shared__ float Bs[2][8][128];
    __shared__ int rowid[128];
    int tid = threadIdx.x;
    int rowBase = blockIdx.x * 128;
    int m = GATHER ? g_cnt : M;
    if (rowBase >= m) return;
    if (tid < 128) {
        int r = rowBase + tid;
        rowid[tid] = (r < m) ? (GATHER ? g_list[r] : r) : -1;
    }
    __syncthreads();

    int ar = tid >> 1, ak = (tid & 1) * 4;   // A tile: row ar (0..127), k off ak
    int br = tid >> 5, bc = (tid & 31) * 4;  // B tile: row br (0..7), col bc
    int tx = tid & 15, ty = tid >> 4;        // thread tile 8x8 at (ty*8, tx*8)
    int arow = rowid[ar];
    const float* Aptr = A + (arow >= 0 ? (size_t)arow * K : 0) + ak;

    float acc[8][8];
#pragma unroll
    for (int i = 0; i < 8; i++)
#pragma unroll
        for (int j = 0; j < 8; j++) acc[i][j] = 0.f;

    const int NK = K / 8;
    float4 aReg, bReg;
    // prefetch tile 0
    aReg = (arow >= 0) ? *(const float4*)(Aptr) : make_float4(0, 0, 0, 0);
    bReg = *(const float4*)(B + br * 128 + bc);
    As[0][ak + 0][ar] = aReg.x; As[0][ak + 1][ar] = aReg.y;
    As[0][ak + 2][ar] = aReg.z; As[0][ak + 3][ar] = aReg.w;
    *(float4*)&Bs[0][br][bc] = bReg;
    __syncthreads();

    for (int t = 0; t < NK; t++) {
        int buf = t & 1;
        if (t + 1 < NK) {
            aReg = (arow >= 0) ? *(const float4*)(Aptr + (t + 1) * 8)
                               : make_float4(0, 0, 0, 0);
            bReg = *(const float4*)(B + (size_t)((t + 1) * 8 + br) * 128 + bc);
        }
#pragma unroll
        for (int kk = 0; kk < 8; kk++) {
            float4 a0 = *(const float4*)&As[buf][kk][ty * 8];
            float4 a1 = *(const float4*)&As[buf][kk][ty * 8 + 4];
            float4 b0 = *(const float4*)&Bs[buf][kk][tx * 8];
            float4 b1 = *(const float4*)&Bs[buf][kk][tx * 8 + 4];
            float av[8] = {a0.x, a0.y, a0.z, a0.w, a1.x, a1.y, a1.z, a1.w};
            float bv[8] = {b0.x, b0.y, b0.z, b0.w, b1.x, b1.y, b1.z, b1.w};
#pragma unroll
            for (int i = 0; i < 8; i++)
#pragma unroll
                for (int j = 0; j < 8; j++) acc[i][j] = fmaf(av[i], bv[j], acc[i][j]);
        }
        if (t + 1 < NK) {
            int nb = buf ^ 1;
            As[nb][ak + 0][ar] = aReg.x; As[nb][ak + 1][ar] = aReg.y;
            As[nb][ak + 2][ar] = aReg.z; As[nb][ak + 3][ar] = aReg.w;
            *(float4*)&Bs[nb][br][bc] = bReg;
        }
        __syncthreads();
    }

#pragma unroll
    for (int i = 0; i < 8; i++) {
        int grow = rowid[ty * 8 + i];
        if (grow >= 0) {
            *(float4*)&Cmat[(size_t)grow * 128 + tx * 8] =
                make_float4(acc[i][0], acc[i][1], acc[i][2], acc[i][3]);
            *(float4*)&Cmat[(size_t)grow * 128 + tx * 8 + 4] =
                make_float4(acc[i][4], acc[i][5], acc[i][6], acc[i][7]);
        }
    }
}

// ---------------- per-node attention coefficients ----------------
template <bool LIST>
__global__ void alpha_kernel(const float* __restrict__ xp,
                             const float* __restrict__ a_src,
                             const float* __restrict__ a_dst) {
    int warp = (blockIdx.x * blockDim.x + threadIdx.x) >> 5;
    int lane = threadIdx.x & 31;
    int n = LIST ? g_cnt : NN;
    if (warp >= n) return;
    int node = LIST ? g_list[warp] : warp;
    float s[4], d[4];
#pragma unroll
    for (int j = 0; j < 4; j++) {
        float v = xp[(size_t)node * HC + j * 32 + lane];
        s[j] = v * a_src[j * 32 + lane];
        d[j] = v * a_dst[j * 32 + lane];
    }
#pragma unroll
    for (int o = 16; o; o >>= 1) {
#pragma unroll
        for (int j = 0; j < 4; j++) {
            s[j] += __shfl_xor_sync(0xffffffffu, s[j], o);
            d[j] += __shfl_xor_sync(0xffffffffu, d[j], o);
        }
    }
    if (lane == 0) {
#pragma unroll
        for (int j = 0; j < 4; j++) {
            g_as[node * HH + j] = s[j];
            g_ad[node * HH + j] = d[j];
        }
    }
}

// ------- softmax + aggregate (one warp per dst node; single pass, no max shift) -------
template <bool ROOTS, bool RELU>
__global__ void agg_kernel(const float* __restrict__ xp,
                           const float* __restrict__ bias,
                           const int* __restrict__ roots,
                           float* __restrict__ out) {
    int warp = (blockIdx.x * blockDim.x + threadIdx.x) >> 5;
    int lane = threadIdx.x & 31;
    int n_items = ROOTS ? 1024 : g_cnt;
    if (warp >= n_items) return;
    int node = ROOTS ? roots[warp] : g_list[warp];
    int beg = g_off[node], end = g_off[node + 1];

    float4 adv = ((const float4*)g_ad)[node];
    int h = lane >> 3;  // 8 lanes per head, 4 floats (float4) per lane
    float myad = (h == 0) ? adv.x : (h == 1) ? adv.y : (h == 2) ? adv.z : adv.w;

    float4 acc = make_float4(0.f, 0.f, 0.f, 0.f);
    float denom = 0.f;
    for (int e = beg; e < end; ++e) {
        int s = g_csr[e];
        float als = g_as[s * HH + h];
        float w = __expf(leaky(als + myad));
        float4 v = ((const float4*)xp)[(size_t)s * 32 + lane];
        acc.x = fmaf(w, v.x, acc.x);
        acc.y = fmaf(w, v.y, acc.y);
        acc.z = fmaf(w, v.z, acc.z);
        acc.w = fmaf(w, v.w, acc.w);
        denom += w;
    }
    float inv = 1.f / (denom + 1e-16f);
    float4 bv = ((const float4*)bias)[lane];
    float4 r;
    r.x = acc.x * inv + bv.x;
    r.y = acc.y * inv + bv.y;
    r.z = acc.z * inv + bv.z;
    r.w = acc.w * inv + bv.w;
    if (RELU) {
        r.x = fmaxf(r.x, 0.f); r.y = fmaxf(r.y, 0.f);
        r.z = fmaxf(r.z, 0.f); r.w = fmaxf(r.w, 0.f);
    }
    int orow = ROOTS ? warp : node;
    ((float4*)out)[(size_t)orow * 32 + lane] = r;
}

// ---------------- launch ----------------
extern "C" void kernel_launch(void* const* d_in, const int* in_sizes, int n_in,
                              void* d_out, int out_size) {
    const float* x     = (const float*)d_in[0];
    const int*   ei    = (const int*)d_in[1];
    const int*   roots = (const int*)d_in[2];
    const float* W1    = (const float*)d_in[3];
    const float* as1   = (const float*)d_in[4];
    const float* ad1   = (const float*)d_in[5];
    const float* b1    = (const float*)d_in[6];
    const float* W2    = (const float*)d_in[7];
    const float* as2   = (const float*)d_in[8];
    const float* ad2   = (const float*)d_in[9];
    const float* b2    = (const float*)d_in[10];
    float* out = (float*)d_out;

    float *p_xp, *p_h;
    cudaGetSymbolAddress((void**)&p_xp, g_xp);
    cudaGetSymbolAddress((void**)&p_h, g_h);

    // frontier: L1set = roots U src(edges -> roots)
    init_kernel<<<(NN + 255) / 256, 256>>>();
    mark_roots_kernel<<<4, 256>>>(roots);
    mark_src_kernel<<<(EE + 255) / 256, 256>>>(ei);
    compact_kernel<<<(NN + 255) / 256, 256>>>();

    // CSR over dst, restricted to dst in L1set (serves both layers)
    count_kernel<<<(TOT + 255) / 256, 256>>>(ei);
    scan_kernel<<<1, 1024>>>();
    fill_kernel<<<(TOT + 255) / 256, 256>>>(ei);

    // layer 1 (xp/alpha for all nodes; aggregation only at L1set)
    gemm_kernel<256, false><<<(NN + 127) / 128, 256>>>(x, W1, p_xp, NN);
    alpha_kernel<false><<<(NN + 7) / 8, 256>>>(p_xp, as1, ad1);
    agg_kernel<false, true><<<(NN + 7) / 8, 256>>>(p_xp, b1, nullptr, p_h);

    // layer 2 (everything restricted to L1set; aggregation only at roots)
    gemm_kernel<128, true><<<(NN + 127) / 128, 256>>>(p_h, W2, p_xp, NN);
    alpha_kernel<true><<<(NN + 7) / 8, 256>>>(p_xp, as2, ad2);
    agg_kernel<true, false><<<(1024 + 7) / 8, 256>>>(p_xp, b2, roots, out);
}

// round 9
// speedup vs baseline: 1.1685x; 1.1545x over previous
#include <cuda_runtime.h>

#define NN 50000
#define EE 800000
#define TOT (EE + NN)
#define HC 128
#define HH 4
#define NEG_SLOPE 0.2f

// ---------------- scratch (device globals; no allocs allowed) ----------------
__device__ float g_xp[(size_t)NN * HC];   // projected features (per layer)
__device__ float g_h[(size_t)NN * HC];    // layer-1 output (post relu)
__device__ float g_as[NN * HH];           // alpha_src per node/head
__device__ float g_ad[NN * HH];           // alpha_dst per node/head
__device__ int   g_deg[NN];
__device__ int   g_start[NN];             // segment start (unordered alloc)
__device__ int   g_pos[NN];
__device__ int   g_csr[TOT];              // src ids grouped by dst (restricted)
__device__ unsigned char g_flagR[NN];     // is root
__device__ unsigned char g_flagL[NN];     // in L1set (roots + sources of roots)
__device__ int   g_list[NN];              // compacted L1set
__device__ int   g_cnt;
__device__ int   g_tot;

__device__ __forceinline__ float leaky(float x) { return x > 0.f ? x : NEG_SLOPE * x; }

// ---------------- frontier marking ----------------
__global__ void init_kernel() {
    int i = blockIdx.x * blockDim.x + threadIdx.x;
    if (i < NN) { g_flagR[i] = 0; g_flagL[i] = 0; g_deg[i] = 0; }
    if (i == 0) { g_cnt = 0; g_tot = 0; }
}

__global__ void mark_roots_kernel(const int* __restrict__ roots) {
    int i = blockIdx.x * blockDim.x + threadIdx.x;
    if (i < 1024) { int r = roots[i]; g_flagR[r] = 1; g_flagL[r] = 1; }
}

__global__ void mark_src_kernel(const int* __restrict__ ei) {
    int e = blockIdx.x * blockDim.x + threadIdx.x;
    if (e >= EE) return;
    int d = ei[EE + e];
    if (g_flagR[d]) g_flagL[ei[e]] = 1;
}

// ---------------- CSR build (restricted to dst in L1set) ----------------
__global__ void count_kernel(const int* __restrict__ ei) {
    int t = blockIdx.x * blockDim.x + threadIdx.x;
    if (t >= TOT) return;
    int d = (t < EE) ? ei[EE + t] : (t - EE);
    if (g_flagL[d]) atomicAdd(&g_deg[d], 1);
}

// compact L1set + allocate CSR segments (order irrelevant; warp-aggregated atomics)
__global__ void compact_off_kernel() {
    int i = blockIdx.x * blockDim.x + threadIdx.x;
    int lane = threadIdx.x & 31;
    bool act = (i < NN) && g_flagL[i];
    unsigned mask = __ballot_sync(0xffffffffu, act);
    int deg = act ? g_deg[i] : 0;
    int x = deg;
#pragma unroll
    for (int o = 1; o < 32; o <<= 1) {
        int y = __shfl_up_sync(0xffffffffu, x, o);
        if (lane >= o) x += y;
    }
    int warpDeg = __shfl_sync(0xffffffffu, x, 31);
    int exclDeg = x - deg;
    int cntPrefix = __popc(mask & ((1u << lane) - 1));
    int warpCnt = __popc(mask);
    int baseCnt = 0, baseOff = 0;
    if (lane == 0 && warpCnt) {
        baseCnt = atomicAdd(&g_cnt, warpCnt);
        baseOff = atomicAdd(&g_tot, warpDeg);
    }
    baseCnt = __shfl_sync(0xffffffffu, baseCnt, 0);
    baseOff = __shfl_sync(0xffffffffu, baseOff, 0);
    if (act) {
        g_list[baseCnt + cntPrefix] = i;
        int st = baseOff + exclDeg;
        g_start[i] = st;
        g_pos[i] = st;
    }
}

__global__ void fill_kernel(const int* __restrict__ ei) {
    int t = blockIdx.x * blockDim.x + threadIdx.x;
    if (t >= TOT) return;
    int s, d;
    if (t < EE) { s = ei[t]; d = ei[EE + t]; }
    else { s = d = t - EE; }
    if (!g_flagL[d]) return;
    int p = atomicAdd(&g_pos[d], 1);
    g_csr[p] = s;
}

// ------- GEMM: C[M,128] = A[M,K] @ B[K,128], fused per-node alpha epilogue -------
// BM=64, BN=128, BK=8, 128 threads, 8x8 per-thread tile, double-buffered.
template <int K, bool GATHER>
__global__ void __launch_bounds__(128, 4)
gemm_kernel(const float* __restrict__ A, const float* __restrict__ B,
            float* __restrict__ Cmat,
            const float* __restrict__ a_src, const float* __restrict__ a_dst, int M) {
    __shared__ float As[2][8][64];
    __shared__ float Bs[2][8][128];
    __shared__ int rowid[64];
    int tid = threadIdx.x;
    int rowBase = blockIdx.x * 64;
    int m = GATHER ? g_cnt : M;
    if (rowBase >= m) return;
    if (tid < 64) {
        int r = rowBase + tid;
        rowid[tid] = (r < m) ? (GATHER ? g_list[r] : r) : -1;
    }
    __syncthreads();

    int ar = tid >> 1, ak = (tid & 1) * 4;   // A tile: row ar (0..63), k off ak
    int tx = tid & 15, ty = tid >> 4;        // thread tile 8x8 at (ty*8, tx*8)
    int arow = rowid[ar];
    const float* Aptr = A + (arow >= 0 ? (size_t)arow * K : 0) + ak;

    // attention weights for this thread's 8 columns (single head: tx>>2)
    float asw[8], adw[8];
    {
        float4 s0 = *(const float4*)(a_src + tx * 8);
        float4 s1 = *(const float4*)(a_src + tx * 8 + 4);
        float4 d0 = *(const float4*)(a_dst + tx * 8);
        float4 d1 = *(const float4*)(a_dst + tx * 8 + 4);
        asw[0]=s0.x; asw[1]=s0.y; asw[2]=s0.z; asw[3]=s0.w;
        asw[4]=s1.x; asw[5]=s1.y; asw[6]=s1.z; asw[7]=s1.w;
        adw[0]=d0.x; adw[1]=d0.y; adw[2]=d0.z; adw[3]=d0.w;
        adw[4]=d1.x; adw[5]=d1.y; adw[6]=d1.z; adw[7]=d1.w;
    }

    float acc[8][8];
#pragma unroll
    for (int i = 0; i < 8; i++)
#pragma unroll
        for (int j = 0; j < 8; j++) acc[i][j] = 0.f;

    const int NK = K / 8;
    float4 aReg, bReg0, bReg1;
    int br0 = tid >> 5, bc0 = (tid & 31) * 4;          // B elems tid
    int br1 = (tid + 128) >> 5, bc1 = (tid & 31) * 4;  // B elems tid+128

    aReg = (arow >= 0) ? *(const float4*)(Aptr) : make_float4(0, 0, 0, 0);
    bReg0 = *(const float4*)(B + br0 * 128 + bc0);
    bReg1 = *(const float4*)(B + br1 * 128 + bc1);
    As[0][ak + 0][ar] = aReg.x; As[0][ak + 1][ar] = aReg.y;
    As[0][ak + 2][ar] = aReg.z; As[0][ak + 3][ar] = aReg.w;
    *(float4*)&Bs[0][br0][bc0] = bReg0;
    *(float4*)&Bs[0][br1][bc1] = bReg1;
    __syncthreads();

    for (int t = 0; t < NK; t++) {
        int buf = t & 1;
        if (t + 1 < NK) {
            aReg = (arow >= 0) ? *(const float4*)(Aptr + (t + 1) * 8)
                               : make_float4(0, 0, 0, 0);
            bReg0 = *(const float4*)(B + (size_t)((t + 1) * 8 + br0) * 128 + bc0);
            bReg1 = *(const float4*)(B + (size_t)((t + 1) * 8 + br1) * 128 + bc1);
        }
#pragma unroll
        for (int kk = 0; kk < 8; kk++) {
            float4 a0 = *(const float4*)&As[buf][kk][ty * 8];
            float4 a1 = *(const float4*)&As[buf][kk][ty * 8 + 4];
            float4 b0 = *(const float4*)&Bs[buf][kk][tx * 8];
            float4 b1 = *(const float4*)&Bs[buf][kk][tx * 8 + 4];
            float av[8] = {a0.x, a0.y, a0.z, a0.w, a1.x, a1.y, a1.z, a1.w};
            float bv[8] = {b0.x, b0.y, b0.z, b0.w, b1.x, b1.y, b1.z, b1.w};
#pragma unroll
            for (int i = 0; i < 8; i++)
#pragma unroll
                for (int j = 0; j < 8; j++) acc[i][j] = fmaf(av[i], bv[j], acc[i][j]);
        }
        if (t + 1 < NK) {
            int nb = buf ^ 1;
            As[nb][ak + 0][ar] = aReg.x; As[nb][ak + 1][ar] = aReg.y;
            As[nb][ak + 2][ar] = aReg.z; As[nb][ak + 3][ar] = aReg.w;
            *(float4*)&Bs[nb][br0][bc0] = bReg0;
            *(float4*)&Bs[nb][br1][bc1] = bReg1;
        }
        __syncthreads();
    }

    int h = tx >> 2;  // head of this thread's 8 columns
#pragma unroll
    for (int i = 0; i < 8; i++) {
        int grow = rowid[ty * 8 + i];
        // per-row partial dot with att vectors (this thread's 8 cols)
        float ps = 0.f, pd = 0.f;
#pragma unroll
        for (int j = 0; j < 8; j++) {
            ps = fmaf(acc[i][j], asw[j], ps);
            pd = fmaf(acc[i][j], adw[j], pd);
        }
        // reduce across the 4 threads covering this head (consecutive lanes)
        ps += __shfl_xor_sync(0xffffffffu, ps, 1);
        pd += __shfl_xor_sync(0xffffffffu, pd, 1);
        ps += __shfl_xor_sync(0xffffffffu, ps, 2);
        pd += __shfl_xor_sync(0xffffffffu, pd, 2);
        if (grow >= 0) {
            *(float4*)&Cmat[(size_t)grow * 128 + tx * 8] =
                make_float4(acc[i][0], acc[i][1], acc[i][2], acc[i][3]);
            *(float4*)&Cmat[(size_t)grow * 128 + tx * 8 + 4] =
                make_float4(acc[i][4], acc[i][5], acc[i][6], acc[i][7]);
            if ((tx & 3) == 0) {
                g_as[grow * HH + h] = ps;
                g_ad[grow * HH + h] = pd;
            }
        }
    }
}

// ------- softmax + aggregate (one warp per dst node; single pass, no max shift) -------
template <bool ROOTS, bool RELU>
__global__ void agg_kernel(const float* __restrict__ xp,
                           const float* __restrict__ bias,
                           const int* __restrict__ roots,
                           float* __restrict__ out) {
    int warp = (blockIdx.x * blockDim.x + threadIdx.x) >> 5;
    int lane = threadIdx.x & 31;
    int n_items = ROOTS ? 1024 : g_cnt;
    if (warp >= n_items) return;
    int node = ROOTS ? roots[warp] : g_list[warp];
    int beg = g_start[node], end = beg + g_deg[node];

    float4 adv = ((const float4*)g_ad)[node];
    int h = lane >> 3;  // 8 lanes per head, 4 floats (float4) per lane
    float myad = (h == 0) ? adv.x : (h == 1) ? adv.y : (h == 2) ? adv.z : adv.w;

    float4 acc = make_float4(0.f, 0.f, 0.f, 0.f);
    float denom = 0.f;
    for (int e = beg; e < end; ++e) {
        int s = g_csr[e];
        float als = g_as[s * HH + h];
        float w = __expf(leaky(als + myad));
        float4 v = ((const float4*)xp)[(size_t)s * 32 + lane];
        acc.x = fmaf(w, v.x, acc.x);
        acc.y = fmaf(w, v.y, acc.y);
        acc.z = fmaf(w, v.z, acc.z);
        acc.w = fmaf(w, v.w, acc.w);
        denom += w;
    }
    float inv = 1.f / (denom + 1e-16f);
    float4 bv = ((const float4*)bias)[lane];
    float4 r;
    r.x = acc.x * inv + bv.x;
    r.y = acc.y * inv + bv.y;
    r.z = acc.z * inv + bv.z;
    r.w = acc.w * inv + bv.w;
    if (RELU) {
        r.x = fmaxf(r.x, 0.f); r.y = fmaxf(r.y, 0.f);
        r.z = fmaxf(r.z, 0.f); r.w = fmaxf(r.w, 0.f);
    }
    int orow = ROOTS ? warp : node;
    ((float4*)out)[(size_t)orow * 32 + lane] = r;
}

// ---------------- launch ----------------
extern "C" void kernel_launch(void* const* d_in, const int* in_sizes, int n_in,
                              void* d_out, int out_size) {
    const float* x     = (const float*)d_in[0];
    const int*   ei    = (const int*)d_in[1];
    const int*   roots = (const int*)d_in[2];
    const float* W1    = (const float*)d_in[3];
    const float* as1   = (const float*)d_in[4];
    const float* ad1   = (const float*)d_in[5];
    const float* b1    = (const float*)d_in[6];
    const float* W2    = (const float*)d_in[7];
    const float* as2   = (const float*)d_in[8];
    const float* ad2   = (const float*)d_in[9];
    const float* b2    = (const float*)d_in[10];
    float* out = (float*)d_out;

    float *p_xp, *p_h;
    cudaGetSymbolAddress((void**)&p_xp, g_xp);
    cudaGetSymbolAddress((void**)&p_h, g_h);

    // frontier: L1set = roots U src(edges -> roots)
    init_kernel<<<(NN + 255) / 256, 256>>>();
    mark_roots_kernel<<<4, 256>>>(roots);
    mark_src_kernel<<<(EE + 255) / 256, 256>>>(ei);

    // CSR over dst, restricted to dst in L1set (serves both layers)
    count_kernel<<<(TOT + 255) / 256, 256>>>(ei);
    compact_off_kernel<<<(NN + 255) / 256, 256>>>();
    fill_kernel<<<(TOT + 255) / 256, 256>>>(ei);

    // layer 1 (xp/alpha for all nodes, alpha fused; aggregation only at L1set)
    gemm_kernel<256, false><<<(NN + 63) / 64, 128>>>(x, W1, p_xp, as1, ad1, NN);
    agg_kernel<false, true><<<(NN + 7) / 8, 256>>>(p_xp, b1, nullptr, p_h);

    // layer 2 (restricted to L1set; aggregation only at roots)
    gemm_kernel<128, true><<<(NN + 63) / 64, 128>>>(p_h, W2, p_xp, as2, ad2, NN);
    agg_kernel<true, false><<<(1024 + 7) / 8, 256>>>(p_xp, b2, roots, out);
}

// round 17
// speedup vs baseline: 2.8554x; 2.4437x over previous
#include <cuda_runtime.h>
#include <cstdint>

#define NN 50000
#define EE 800000
#define TOT (EE + NN)
#define HC 128
#define HH 4
#define NEG_SLOPE 0.2f

// ---------------- scratch (device globals; no allocs allowed) ----------------
__device__ float g_xp[(size_t)NN * HC];   // projected features (per layer)
__device__ float g_h[(size_t)NN * HC];    // layer-1 output (post relu)
__device__ float g_as[NN * HH];           // alpha_src per node/head
__device__ float g_ad[NN * HH];           // alpha_dst per node/head
__device__ int   g_deg[NN];
__device__ int   g_start[NN];             // segment start (unordered alloc)
__device__ int   g_pos[NN];
__device__ int   g_csr[TOT];              // src ids grouped by dst (restricted)
__device__ unsigned char g_flagR[NN];     // is root
__device__ unsigned char g_flagL[NN];     // in L1set (roots + sources of roots)
__device__ int   g_list[NN];              // compacted L1set
__device__ int   g_cnt;
__device__ int   g_tot;

__device__ __forceinline__ float leaky(float x) { return x > 0.f ? x : NEG_SLOPE * x; }

__device__ __forceinline__ uint32_t f2tf(float x) {
    uint32_t r;
    asm("cvt.rna.tf32.f32 %0, %1;" : "=r"(r) : "f"(x));
    return r;
}

#define MMA_TF32(c, a0, a1, a2, a3, b0, b1)                                  \
    asm volatile(                                                            \
        "mma.sync.aligned.m16n8k8.row.col.f32.tf32.tf32.f32 "               \
        "{%0,%1,%2,%3}, {%4,%5,%6,%7}, {%8,%9}, {%0,%1,%2,%3};"             \
        : "+f"((c)[0]), "+f"((c)[1]), "+f"((c)[2]), "+f"((c)[3])            \
        : "r"(a0), "r"(a1), "r"(a2), "r"(a3), "r"(b0), "r"(b1))

// ---------------- frontier marking ----------------
__global__ void init_kernel() {
    int i = blockIdx.x * blockDim.x + threadIdx.x;
    if (i < NN) { g_flagR[i] = 0; g_flagL[i] = 0; g_deg[i] = 0; }
    if (i == 0) { g_cnt = 0; g_tot = 0; }
}

__global__ void mark_roots_kernel(const int* __restrict__ roots) {
    int i = blockIdx.x * blockDim.x + threadIdx.x;
    if (i < 1024) { int r = roots[i]; g_flagR[r] = 1; g_flagL[r] = 1; }
}

__global__ void mark_src_kernel(const int* __restrict__ ei) {
    int e = blockIdx.x * blockDim.x + threadIdx.x;
    if (e >= EE) return;
    int d = ei[EE + e];
    if (g_flagR[d]) g_flagL[ei[e]] = 1;
}

// ---------------- CSR build (restricted to dst in L1set) ----------------
__global__ void count_kernel(const int* __restrict__ ei) {
    int t = blockIdx.x * blockDim.x + threadIdx.x;
    if (t >= EE) return;
    int d = ei[EE + t];
    if (g_flagL[d]) atomicAdd(&g_deg[d], 1);
}

// compact L1set + allocate CSR segments + place self-loop (order irrelevant)
__global__ void compact_off_kernel() {
    int i = blockIdx.x * blockDim.x + threadIdx.x;
    int lane = threadIdx.x & 31;
    bool act = (i < NN) && g_flagL[i];
    int deg = act ? (g_deg[i] + 1) : 0;   // +1: self-loop
    unsigned mask = __ballot_sync(0xffffffffu, act);
    int x = deg;
#pragma unroll
    for (int o = 1; o < 32; o <<= 1) {
        int y = __shfl_up_sync(0xffffffffu, x, o);
        if (lane >= o) x += y;
    }
    int warpDeg = __shfl_sync(0xffffffffu, x, 31);
    int exclDeg = x - deg;
    int cntPrefix = __popc(mask & ((1u << lane) - 1));
    int warpCnt = __popc(mask);
    int baseCnt = 0, baseOff = 0;
    if (lane == 0 && warpCnt) {
        baseCnt = atomicAdd(&g_cnt, warpCnt);
        baseOff = atomicAdd(&g_tot, warpDeg);
    }
    baseCnt = __shfl_sync(0xffffffffu, baseCnt, 0);
    baseOff = __shfl_sync(0xffffffffu, baseOff, 0);
    if (act) {
        g_list[baseCnt + cntPrefix] = i;
        int st = baseOff + exclDeg;
        g_start[i] = st;
        g_deg[i] = deg;        // full degree incl. self-loop
        g_csr[st] = i;         // self-loop entry
        g_pos[i] = st + 1;
    }
}

__global__ void fill_kernel(const int* __restrict__ ei) {
    int t = blockIdx.x * blockDim.x + threadIdx.x;
    if (t >= EE) return;
    int d = ei[EE + t];
    if (!g_flagL[d]) return;
    int p = atomicAdd(&g_pos[d], 1);
    g_csr[p] = ei[t];
}

// ------- layer-1 GEMM (tf32 tensor cores): C[NN,128] = A[NN,256] @ B[256,128] -------
// BM=64, BN=128, BK=16, 128 threads (4 warps), warp w owns cols [w*32,w*32+32) = head w.
// cp.async double-buffered; conflict-free smem (As stride 20, Bs stride 136).
// Fused alpha epilogue: g_as/g_ad written per node/head.
__global__ void __launch_bounds__(128, 4)
gemm1_tf32_kernel(const float* __restrict__ A, const float* __restrict__ B,
                  float* __restrict__ Cmat,
                  const float* __restrict__ a_src, const float* __restrict__ a_dst) {
    const int K = 256;
    const int NKS = K / 16;
    __shared__ float As[2][64][20];
    __shared__ float Bs[2][16][136];
    int tid = threadIdx.x;
    int rowBase = blockIdx.x * 64;
    int w = tid >> 5, lane = tid & 31;
    int grp = lane >> 2, qid = lane & 3;

    // per-thread load coords
    int r0i = (tid * 2) >> 2, kp0 = (tid * 2) & 3;
    int r1i = (tid * 2 + 1) >> 2, kp1 = (tid * 2 + 1) & 3;
    int ar0 = rowBase + r0i; if (ar0 >= NN) ar0 = 0;
    int ar1 = rowBase + r1i; if (ar1 >= NN) ar1 = 0;
    const float* aSrc0 = A + (size_t)ar0 * K + kp0 * 4;
    const float* aSrc1 = A + (size_t)ar1 * K + kp1 * 4;

    float acc[4][4][4];
#pragma unroll
    for (int mi = 0; mi < 4; mi++)
#pragma unroll
        for (int ni = 0; ni < 4; ni++)
#pragma unroll
            for (int q = 0; q < 4; q++) acc[mi][ni][q] = 0.f;

    auto issue_stage = [&](int t, int buf) {
        int k0 = t * 16;
        {
            uint32_t dst = (uint32_t)__cvta_generic_to_shared(&As[buf][r0i][kp0 * 4]);
            asm volatile("cp.async.cg.shared.global [%0], [%1], 16;" ::"r"(dst),
                         "l"(aSrc0 + k0) : "memory");
            dst = (uint32_t)__cvta_generic_to_shared(&As[buf][r1i][kp1 * 4]);
            asm volatile("cp.async.cg.shared.global [%0], [%1], 16;" ::"r"(dst),
                         "l"(aSrc1 + k0) : "memory");
        }
#pragma unroll
        for (int i = 0; i < 4; i++) {
            int idx = tid + i * 128;
            int k = idx >> 5, n4 = idx & 31;
            uint32_t dst = (uint32_t)__cvta_generic_to_shared(&Bs[buf][k][n4 * 4]);
            asm volatile("cp.async.cg.shared.global [%0], [%1], 16;" ::"r"(dst),
                         "l"(B + (size_t)(k0 + k) * 128 + n4 * 4) : "memory");
        }
        asm volatile("cp.async.commit_group;" ::: "memory");
    };

    issue_stage(0, 0);
#pragma unroll 1
    for (int t = 0; t < NKS; t++) {
        int buf = t & 1;
        if (t + 1 < NKS) {
            issue_stage(t + 1, buf ^ 1);
            asm volatile("cp.async.wait_group 1;" ::: "memory");
        } else {
            asm volatile("cp.async.wait_group 0;" ::: "memory");
        }
        __syncthreads();
#pragma unroll
        for (int kc = 0; kc < 16; kc += 8) {
            uint32_t bf[4][2];
#pragma unroll
            for (int ni = 0; ni < 4; ni++) {
                int n = w * 32 + ni * 8 + grp;
                bf[ni][0] = f2tf(Bs[buf][kc + qid][n]);
                bf[ni][1] = f2tf(Bs[buf][kc + qid + 4][n]);
            }
#pragma unroll
            for (int mi = 0; mi < 4; mi++) {
                int r = mi * 16 + grp;
                uint32_t a0 = f2tf(As[buf][r][kc + qid]);
                uint32_t a1 = f2tf(As[buf][r + 8][kc + qid]);
                uint32_t a2 = f2tf(As[buf][r][kc + qid + 4]);
                uint32_t a3 = f2tf(As[buf][r + 8][kc + qid + 4]);
#pragma unroll
                for (int ni = 0; ni < 4; ni++)
                    MMA_TF32(acc[mi][ni], a0, a1, a2, a3, bf[ni][0], bf[ni][1]);
            }
        }
        __syncthreads();
    }

    // epilogue: store C + fused alpha (head = w)
    float as0[4], as1[4], ad0[4], ad1[4];
#pragma unroll
    for (int ni = 0; ni < 4; ni++) {
        int c = w * 32 + ni * 8 + qid * 2;
        as0[ni] = a_src[c]; as1[ni] = a_src[c + 1];
        ad0[ni] = a_dst[c]; ad1[ni] = a_dst[c + 1];
    }
#pragma unroll
    for (int mi = 0; mi < 4; mi++) {
        int r0 = rowBase + mi * 16 + grp;
        int r1 = r0 + 8;
        float ps0 = 0.f, pd0 = 0.f, ps1 = 0.f, pd1 = 0.f;
#pragma unroll
        for (int ni = 0; ni < 4; ni++) {
            ps0 += acc[mi][ni][0] * as0[ni] + acc[mi][ni][1] * as1[ni];
            pd0 += acc[mi][ni][0] * ad0[ni] + acc[mi][ni][1] * ad1[ni];
            ps1 += acc[mi][ni][2] * as0[ni] + acc[mi][ni][3] * as1[ni];
            pd1 += acc[mi][ni][2] * ad0[ni] + acc[mi][ni][3] * ad1[ni];
        }
#pragma unroll
        for (int o = 1; o <= 2; o <<= 1) {
            ps0 += __shfl_xor_sync(0xffffffffu, ps0, o);
            pd0 += __shfl_xor_sync(0xffffffffu, pd0, o);
            ps1 += __shfl_xor_sync(0xffffffffu, ps1, o);
            pd1 += __shfl_xor_sync(0xffffffffu, pd1, o);
        }
        if (r0 < NN) {
#pragma unroll
            for (int ni = 0; ni < 4; ni++) {
                float2 v = make_float2(acc[mi][ni][0], acc[mi][ni][1]);
                *(float2*)&Cmat[(size_t)r0 * 128 + w * 32 + ni * 8 + qid * 2] = v;
            }
            if (qid == 0) { g_as[r0 * HH + w] = ps0; g_ad[r0 * HH + w] = pd0; }
        }
        if (r1 < NN) {
#pragma unroll
            for (int ni = 0; ni < 4; ni++) {
                float2 v = make_float2(acc[mi][ni][2], acc[mi][ni][3]);
                *(float2*)&Cmat[(size_t)r1 * 128 + w * 32 + ni * 8 + qid * 2] = v;
            }
            if (qid == 0) { g_as[r1 * HH + w] = ps1; g_ad[r1 * HH + w] = pd1; }
        }
    }
}

// ------- layer-2 GEMM (fp32 FFMA, row gather): C = A[g_list] @ B, fused alpha -------
// BM=64, BN=128, BK=8, 128 threads, 8x8 per-thread tile, double-buffered.
__global__ void __launch_bounds__(128, 4)
gemm2_kernel(const float* __restrict__ A, const float* __restrict__ B,
             float* __restrict__ Cmat,
             const float* __restrict__ a_src, const float* __restrict__ a_dst) {
    const int K = 128;
    __shared__ float As[2][8][64];
    __shared__ float Bs[2][8][128];
    __shared__ int rowid[64];
    int tid = threadIdx.x;
    int rowBase = blockIdx.x * 64;
    int m = g_cnt;
    if (rowBase >= m) return;
    if (tid < 64) {
        int r = rowBase + tid;
        rowid[tid] = (r < m) ? g_list[r] : -1;
    }
    __syncthreads();

    int ar = tid >> 1, ak = (tid & 1) * 4;
    int tx = tid & 15, ty = tid >> 4;
    int arow = rowid[ar];
    const float* Aptr = A + (arow >= 0 ? (size_t)arow * K : 0) + ak;

    float asw[8], adw[8];
    {
        float4 s0 = *(const float4*)(a_src + tx * 8);
        float4 s1 = *(const float4*)(a_src + tx * 8 + 4);
        float4 d0 = *(const float4*)(a_dst + tx * 8);
        float4 d1 = *(const float4*)(a_dst + tx * 8 + 4);
        asw[0]=s0.x; asw[1]=s0.y; asw[2]=s0.z; asw[3]=s0.w;
        asw[4]=s1.x; asw[5]=s1.y; asw[6]=s1.z; asw[7]=s1.w;
        adw[0]=d0.x; adw[1]=d0.y; adw[2]=d0.z; adw[3]=d0.w;
        adw[4]=d1.x; adw[5]=d1.y; adw[6]=d1.z; adw[7]=d1.w;
    }

    float acc[8][8];
#pragma unroll
    for (int i = 0; i < 8; i++)
#pragma unroll
        for (int j = 0; j < 8; j++) acc[i][j] = 0.f;

    const int NK = K / 8;
    float4 aReg, bReg0, bReg1;
    int br0 = tid >> 5, bc0 = (tid & 31) * 4;
    int br1 = (tid + 128) >> 5, bc1 = (tid & 31) * 4;

    aReg = (arow >= 0) ? *(const float4*)(Aptr) : make_float4(0, 0, 0, 0);
    bReg0 = *(const float4*)(B + br0 * 128 + bc0);
    bReg1 = *(const float4*)(B + br1 * 128 + bc1);
    As[0][ak + 0][ar] = aReg.x; As[0][ak + 1][ar] = aReg.y;
    As[0][ak + 2][ar] = aReg.z; As[0][ak + 3][ar] = aReg.w;
    *(float4*)&Bs[0][br0][bc0] = bReg0;
    *(float4*)&Bs[0][br1][bc1] = bReg1;
    __syncthreads();

    for (int t = 0; t < NK; t++) {
        int buf = t & 1;
        if (t + 1 < NK) {
            aReg = (arow >= 0) ? *(const float4*)(Aptr + (t + 1) * 8)
                               : make_float4(0, 0, 0, 0);
            bReg0 = *(const float4*)(B + (size_t)((t + 1) * 8 + br0) * 128 + bc0);
            bReg1 = *(const float4*)(B + (size_t)((t + 1) * 8 + br1) * 128 + bc1);
        }
#pragma unroll
        for (int kk = 0; kk < 8; kk++) {
            float4 a0 = *(const float4*)&As[buf][kk][ty * 8];
            float4 a1 = *(const float4*)&As[buf][kk][ty * 8 + 4];
            float4 b0 = *(const float4*)&Bs[buf][kk][tx * 8];
            float4 b1 = *(const float4*)&Bs[buf][kk][tx * 8 + 4];
            float av[8] = {a0.x, a0.y, a0.z, a0.w, a1.x, a1.y, a1.z, a1.w};
            float bv[8] = {b0.x, b0.y, b0.z, b0.w, b1.x, b1.y, b1.z, b1.w};
#pragma unroll
            for (int i = 0; i < 8; i++)
#pragma unroll
                for (int j = 0; j < 8; j++) acc[i][j] = fmaf(av[i], bv[j], acc[i][j]);
        }
        if (t + 1 < NK) {
            int nb = buf ^ 1;
            As[nb][ak + 0][ar] = aReg.x; As[nb][ak + 1][ar] = aReg.y;
            As[nb][ak + 2][ar] = aReg.z; As[nb][ak + 3][ar] = aReg.w;
            *(float4*)&Bs[nb][br0][bc0] = bReg0;
            *(float4*)&Bs[nb][br1][bc1] = bReg1;
        }
        __syncthreads();
    }

    int h = tx >> 2;
#pragma unroll
    for (int i = 0; i < 8; i++) {
        int grow = rowid[ty * 8 + i];
        float ps = 0.f, pd = 0.f;
#pragma unroll
        for (int j = 0; j < 8; j++) {
            ps = fmaf(acc[i][j], asw[j], ps);
            pd = fmaf(acc[i][j], adw[j], pd);
        }
        ps += __shfl_xor_sync(0xffffffffu, ps, 1);
        pd += __shfl_xor_sync(0xffffffffu, pd, 1);
        ps += __shfl_xor_sync(0xffffffffu, ps, 2);
        pd += __shfl_xor_sync(0xffffffffu, pd, 2);
        if (grow >= 0) {
            *(float4*)&Cmat[(size_t)grow * 128 + tx * 8] =
                make_float4(acc[i][0], acc[i][1], acc[i][2], acc[i][3]);
            *(float4*)&Cmat[(size_t)grow * 128 + tx * 8 + 4] =
                make_float4(acc[i][4], acc[i][5], acc[i][6], acc[i][7]);
            if ((tx & 3) == 0) {
                g_as[grow * HH + h] = ps;
                g_ad[grow * HH + h] = pd;
            }
        }
    }
}

// ------- softmax + aggregate (one warp per dst node; single pass, no max shift) -------
template <bool ROOTS, bool RELU>
__global__ void agg_kernel(const float* __restrict__ xp,
                           const float* __restrict__ bias,
                           const int* __restrict__ roots,
                           float* __restrict__ out) {
    int warp = (blockIdx.x * blockDim.x + threadIdx.x) >> 5;
    int lane = threadIdx.x & 31;
    int n_items = ROOTS ? 1024 : g_cnt;
    if (warp >= n_items) return;
    int node = ROOTS ? roots[warp] : g_list[warp];
    int beg = g_start[node], end = beg + g_deg[node];

    float4 adv = ((const float4*)g_ad)[node];
    int h = lane >> 3;
    float myad = (h == 0) ? adv.x : (h == 1) ? adv.y : (h == 2) ? adv.z : adv.w;

    float4 acc = make_float4(0.f, 0.f, 0.f, 0.f);
    float denom = 0.f;
    for (int e = beg; e < end; ++e) {
        int s = g_csr[e];
        float als = g_as[s * HH + h];
        float w = __expf(leaky(als + myad));
        float4 v = ((const float4*)xp)[(size_t)s * 32 + lane];
        acc.x = fmaf(w, v.x, acc.x);
        acc.y = fmaf(w, v.y, acc.y);
        acc.z = fmaf(w, v.z, acc.z);
        acc.w = fmaf(w, v.w, acc.w);
        denom += w;
    }
    float inv = 1.f / (denom + 1e-16f);
    float4 bv = ((const float4*)bias)[lane];
    float4 r;
    r.x = acc.x * inv + bv.x;
    r.y = acc.y * inv + bv.y;
    r.z = acc.z * inv + bv.z;
    r.w = acc.w * inv + bv.w;
    if (RELU) {
        r.x = fmaxf(r.x, 0.f); r.y = fmaxf(r.y, 0.f);
        r.z = fmaxf(r.z, 0.f); r.w = fmaxf(r.w, 0.f);
    }
    int orow = ROOTS ? warp : node;
    ((float4*)out)[(size_t)orow * 32 + lane] = r;
}

// ---------------- launch ----------------
extern "C" void kernel_launch(void* const* d_in, const int* in_sizes, int n_in,
                              void* d_out, int out_size) {
    const float* x     = (const float*)d_in[0];
    const int*   ei    = (const int*)d_in[1];
    const int*   roots = (const int*)d_in[2];
    const float* W1    = (const float*)d_in[3];
    const float* as1   = (const float*)d_in[4];
    const float* ad1   = (const float*)d_in[5];
    const float* b1    = (const float*)d_in[6];
    const float* W2    = (const float*)d_in[7];
    const float* as2   = (const float*)d_in[8];
    const float* ad2   = (const float*)d_in[9];
    const float* b2    = (const float*)d_in[10];
    float* out = (float*)d_out;

    float *p_xp, *p_h;
    cudaGetSymbolAddress((void**)&p_xp, g_xp);
    cudaGetSymbolAddress((void**)&p_h, g_h);

    // frontier: L1set = roots U src(edges -> roots)
    init_kernel<<<(NN + 255) / 256, 256>>>();
    mark_roots_kernel<<<4, 256>>>(roots);
    mark_src_kernel<<<(EE + 255) / 256, 256>>>(ei);

    // CSR over dst, restricted to dst in L1set (self-loops placed in compact)
    count_kernel<<<(EE + 255) / 256, 256>>>(ei);
    compact_off_kernel<<<(NN + 255) / 256, 256>>>();
    fill_kernel<<<(EE + 255) / 256, 256>>>(ei);

    // layer 1 (tf32 tensor-core GEMM + fused alpha; aggregation only at L1set)
    gemm1_tf32_kernel<<<(NN + 63) / 64, 128>>>(x, W1, p_xp, as1, ad1);
    agg_kernel<false, true><<<(NN + 7) / 8, 256>>>(p_xp, b1, nullptr, p_h);

    // layer 2 (fp32 FFMA gather GEMM + fused alpha; aggregation only at roots)
    gemm2_kernel<<<(NN + 63) / 64, 128>>>(p_h, W2, p_xp, as2, ad2);
    agg_kernel<true, false><<<(1024 + 7) / 8, 256>>>(p_xp, b2, roots, out);
}